// round 16
// baseline (speedup 1.0000x reference)
#include <cuda_runtime.h>
#include <cuda_fp16.h>
#include <stdint.h>
#include <math.h>

#define NDIM  256
#define NROT  32640
#define BATCH 65536

// ---------------- scratch (device globals; no allocation allowed) ----------
__device__ float2 g_cs1[NROT];
__device__ float2 g_cs2[NROT];
__device__ float  g_chunks[2 * 4 * NDIM * NDIM];   // 4 chunk products per mat
__device__ float  g_q[2 * 2 * NDIM * NDIM];        // pair products
__device__ float  g_M1[NDIM * NDIM];
__device__ float  g_M2C[NDIM * NDIM];              // M2 * diag(cos(ph))
__device__ float  g_M2S[NDIM * NDIM];              // M2 * diag(sin(ph))
__device__ float  g_norm2[BATCH];

__device__ __half g_Xhi[BATCH * NDIM];             // fp16 X
__device__ __half g_Whi[2 * NDIM * NDIM];          // N'=512 (even=Re, odd=Im)

// 4 balanced chunks (~8160 rotations each)
__constant__ int c_bound[5] = {0, 34, 74, 127, 255};

// ---------------- PTX helpers ------------------------------------------------
__device__ __forceinline__ uint32_t smem_u32(const void* p) {
    uint32_t a;
    asm("{ .reg .u64 t; cvta.to.shared.u64 t, %1; cvt.u32.u64 %0, t; }"
        : "=r"(a) : "l"(p));
    return a;
}

__device__ __forceinline__ void cp16(uint32_t dst, const void* src) {
    asm volatile("cp.async.cg.shared.global [%0], [%1], 16;" :: "r"(dst), "l"(src));
}
__device__ __forceinline__ void cp_commit() {
    asm volatile("cp.async.commit_group;");
}
template <int N>
__device__ __forceinline__ void cp_wait() {
    asm volatile("cp.async.wait_group %0;" :: "n"(N));
}

__device__ __forceinline__ void mma16816(float* d, const uint32_t* a,
                                         uint32_t b0, uint32_t b1) {
    asm volatile(
        "mma.sync.aligned.m16n8k16.row.col.f32.f16.f16.f32 "
        "{%0,%1,%2,%3}, {%4,%5,%6,%7}, {%8,%9}, {%0,%1,%2,%3};"
        : "+f"(d[0]), "+f"(d[1]), "+f"(d[2]), "+f"(d[3])
        : "r"(a[0]), "r"(a[1]), "r"(a[2]), "r"(a[3]), "r"(b0), "r"(b1));
}

__device__ __forceinline__ void ldsm_x4(uint32_t& r0, uint32_t& r1,
                                        uint32_t& r2, uint32_t& r3,
                                        uint32_t addr) {
    asm volatile("ldmatrix.sync.aligned.m8n8.x4.shared.b16 {%0,%1,%2,%3}, [%4];"
                 : "=r"(r0), "=r"(r1), "=r"(r2), "=r"(r3) : "r"(addr));
}

// ---------------- 1) fused: X fp16 + row norms  |  sincos --------------------
// blocks [0, 8192): convx_norm (8 rows each).  blocks [8192, 8192+128): sincos.
__global__ void k_misc(const float4* __restrict__ x4,
                       const float* __restrict__ rots1,
                       const float* __restrict__ rots2) {
    if (blockIdx.x >= 8192) {
        int i = (blockIdx.x - 8192) * 256 + threadIdx.x;
        if (i < NROT) {
            float s, c;
            sincosf(rots1[i], &s, &c);
            g_cs1[i] = make_float2(c, s);
            sincosf(rots2[i], &s, &c);
            g_cs2[i] = make_float2(c, s);
        }
        return;
    }
    int w = threadIdx.x >> 5;
    int lane = threadIdx.x & 31;
    int row = blockIdx.x * 8 + w;
    const float4* p = x4 + (size_t)row * 64;
    float4 va = p[lane];
    float4 vb = p[lane + 32];

    float s = va.x * va.x + va.y * va.y + va.z * va.z + va.w * va.w
            + vb.x * vb.x + vb.y * vb.y + vb.z * vb.z + vb.w * vb.w;
    #pragma unroll
    for (int o = 16; o; o >>= 1) s += __shfl_xor_sync(0xffffffffu, s, o);
    if (lane == 0) g_norm2[row] = s;

    __half2* Ph = (__half2*)(g_Xhi + (size_t)row * NDIM);
    #pragma unroll
    for (int half = 0; half < 2; ++half) {
        float4 v = half ? vb : va;
        int base = (lane + half * 32) * 2;
        Ph[base + 0] = __halves2half2(__float2half(v.x), __float2half(v.y));
        Ph[base + 1] = __halves2half2(__float2half(v.z), __float2half(v.w));
    }
}

// ---------------- 2a) build 4 chunk products per matrix ----------------------
// 64 blocks x 32 threads: block = (mat, chunk, colgroup).
__global__ void k_build_chunk() {
    __shared__ float col[NDIM * 32];
    int t = threadIdx.x;
    int b = blockIdx.x;
    int mat = b >> 5;
    int rem = b & 31;
    int chunk = rem >> 3;
    int cg = rem & 7;
    int c = cg * 32 + t;

    int a = c_bound[chunk];
    int e = c_bound[chunk + 1];

    const float2* __restrict__ cs = mat ? g_cs2 : g_cs1;
    float* __restrict__ P = g_chunks + (size_t)(mat * 4 + chunk) * (NDIM * NDIM);

    for (int r = 0; r < NDIM; ++r)
        col[r * 32 + t] = (r == c) ? 1.0f : 0.0f;

    int ridx = a * 255 - (a * (a - 1)) / 2;
    for (int i = a; i < e; ++i) {
        float acc = col[i * 32 + t];
        #pragma unroll 8
        for (int j = i + 1; j < NDIM; ++j) {
            float2 v = __ldg(&cs[ridx]);
            ++ridx;
            float vj = col[j * 32 + t];
            col[j * 32 + t] = v.y * acc + v.x * vj;
            acc = v.x * acc - v.y * vj;
        }
        col[i * 32 + t] = acc;
    }

    for (int r = 0; r < NDIM; ++r)
        P[r * NDIM + c] = col[r * 32 + t];
}

// ---------------- 2b) combine steps (register-prefetch fp32 GEMM core) -------
// step 0 (cA, z=0..3): q[mat][p] = P[mat][2p+1] * P[mat][2p]
// step 1 (cB, z=0..1): M = q[mat][1] * q[mat][0];
//                      mat0 -> g_M1;  mat1 -> g_M2C, g_M2S (phase-scaled cols)
// step 2 (cC, z=0..1): z0: Whi(even rows) = M2C*M1; z1: Whi(odd) = M2S*M1 (fp16)
__global__ __launch_bounds__(256) void k_combine(int step,
                                                 const float* __restrict__ phases) {
    __shared__ float Asm[64][33];
    __shared__ float Bsm[32][65];

    int z = blockIdx.z;
    const float *A, *B;
    if (step == 0) {
        int mat = z >> 1, p = z & 1;
        A = g_chunks + (size_t)(mat * 4 + 2 * p + 1) * (NDIM * NDIM);
        B = g_chunks + (size_t)(mat * 4 + 2 * p) * (NDIM * NDIM);
    } else if (step == 1) {
        A = g_q + (size_t)(z * 2 + 1) * (NDIM * NDIM);
        B = g_q + (size_t)(z * 2 + 0) * (NDIM * NDIM);
    } else {
        A = z ? g_M2S : g_M2C;
        B = g_M1;
    }

    int tid = threadIdx.x;
    int tx = tid & 15, ty = tid >> 4;
    int row0 = blockIdx.y * 64;
    int col0 = blockIdx.x * 64;

    int ar = tid >> 2, aq = tid & 3;
    int br = tid >> 3, bq = tid & 7;

    float acc[4][4];
    #pragma unroll
    for (int i = 0; i < 4; ++i)
        #pragma unroll
        for (int j = 0; j < 4; ++j) acc[i][j] = 0.f;

    float4 pa0, pa1, pb0, pb1;
    {
        const float4* ap = (const float4*)&A[(row0 + ar) * NDIM];
        pa0 = ap[aq * 2]; pa1 = ap[aq * 2 + 1];
        const float4* bp = (const float4*)&B[(size_t)br * NDIM + col0];
        pb0 = bp[bq * 2]; pb1 = bp[bq * 2 + 1];
    }

    for (int kc = 0; kc < 8; ++kc) {
        __syncthreads();
        Asm[ar][aq * 8 + 0] = pa0.x; Asm[ar][aq * 8 + 1] = pa0.y;
        Asm[ar][aq * 8 + 2] = pa0.z; Asm[ar][aq * 8 + 3] = pa0.w;
        Asm[ar][aq * 8 + 4] = pa1.x; Asm[ar][aq * 8 + 5] = pa1.y;
        Asm[ar][aq * 8 + 6] = pa1.z; Asm[ar][aq * 8 + 7] = pa1.w;
        Bsm[br][bq * 8 + 0] = pb0.x; Bsm[br][bq * 8 + 1] = pb0.y;
        Bsm[br][bq * 8 + 2] = pb0.z; Bsm[br][bq * 8 + 3] = pb0.w;
        Bsm[br][bq * 8 + 4] = pb1.x; Bsm[br][bq * 8 + 5] = pb1.y;
        Bsm[br][bq * 8 + 6] = pb1.z; Bsm[br][bq * 8 + 7] = pb1.w;
        __syncthreads();

        if (kc < 7) {
            const float4* ap = (const float4*)&A[(row0 + ar) * NDIM + (kc + 1) * 32];
            pa0 = ap[aq * 2]; pa1 = ap[aq * 2 + 1];
            const float4* bp = (const float4*)&B[(size_t)((kc + 1) * 32 + br) * NDIM + col0];
            pb0 = bp[bq * 2]; pb1 = bp[bq * 2 + 1];
        }

        #pragma unroll 8
        for (int m = 0; m < 32; ++m) {
            float arr[4], brr[4];
            #pragma unroll
            for (int i = 0; i < 4; ++i) arr[i] = Asm[ty * 4 + i][m];
            #pragma unroll
            for (int j = 0; j < 4; ++j) brr[j] = Bsm[m][tx * 4 + j];
            #pragma unroll
            for (int i = 0; i < 4; ++i)
                #pragma unroll
                for (int j = 0; j < 4; ++j) acc[i][j] += arr[i] * brr[j];
        }
    }

    // epilogue per step
    if (step == 0) {
        float* C = g_q + (size_t)z * (NDIM * NDIM);
        #pragma unroll
        for (int i = 0; i < 4; ++i)
            #pragma unroll
            for (int j = 0; j < 4; ++j)
                C[(size_t)(row0 + ty * 4 + i) * NDIM + col0 + tx * 4 + j] = acc[i][j];
    } else if (step == 1) {
        if (z == 0) {
            #pragma unroll
            for (int i = 0; i < 4; ++i)
                #pragma unroll
                for (int j = 0; j < 4; ++j)
                    g_M1[(size_t)(row0 + ty * 4 + i) * NDIM + col0 + tx * 4 + j] = acc[i][j];
        } else {
            float cp[4], sp[4];
            #pragma unroll
            for (int j = 0; j < 4; ++j)
                sincosf(phases[col0 + tx * 4 + j], &sp[j], &cp[j]);
            #pragma unroll
            for (int i = 0; i < 4; ++i)
                #pragma unroll
                for (int j = 0; j < 4; ++j) {
                    size_t o = (size_t)(row0 + ty * 4 + i) * NDIM + col0 + tx * 4 + j;
                    g_M2C[o] = acc[i][j] * cp[j];
                    g_M2S[o] = acc[i][j] * sp[j];
                }
        }
    } else {
        // W rows interleaved: row n -> g_Whi row 2n+z  (z0=Re, z1=Im)
        #pragma unroll
        for (int i = 0; i < 4; ++i)
            #pragma unroll
            for (int j = 0; j < 4; ++j)
                g_Whi[(size_t)(2 * (row0 + ty * 4 + i) + z) * NDIM + col0 + tx * 4 + j] =
                    __float2half(acc[i][j]);
    }
}

// ---------------- 5) classic-MMA GEMM, fp16 1-pass, BK=64, 3-stage ring ------
#define AST   72                         // fp16 row stride
#define TILEB (128 * AST * 2)            // 18432 B per operand tile
#define STGB  (2 * TILEB)                // 36864 B per stage (A+B)
#define GEMM_SMEM (3 * STGB)             // 110592 B

__global__ __launch_bounds__(256, 2) void k_gemm_tc(float* __restrict__ out) {
    extern __shared__ __align__(16) char smem[];
    uint32_t sb = smem_u32(smem);

    int tid = threadIdx.x;
    int wid = tid >> 5, lane = tid & 31;
    int warp_m = wid >> 2;          // 0..1
    int warp_n = wid & 3;           // 0..3
    int mtile = blockIdx.x;         // 0..511
    int ntile = blockIdx.y;         // 0..3

    float acc[4][4][4];
    #pragma unroll
    for (int mt = 0; mt < 4; ++mt)
        #pragma unroll
        for (int nt = 0; nt < 4; ++nt)
            #pragma unroll
            for (int q = 0; q < 4; ++q) acc[mt][nt][q] = 0.f;

    int a_row  = warp_m * 64 + (lane & 15);
    int a_colp = (lane >> 4) * 8;
    int b_rowl = ((lane >> 4) << 3) + (lane & 7);
    int b_colp = ((lane >> 3) & 1) * 8;

    int ld_r = tid >> 3;            // row 0..31 (+32*i)
    int ld_c = tid & 7;             // chunk 0..7
    uint32_t st_off = (uint32_t)(ld_r * (AST * 2) + ld_c * 16);

    auto load_stage = [&](int it, int buf) {
        int kc = it * 64;
        uint32_t ab = sb + (uint32_t)buf * STGB;
        uint32_t bb = ab + TILEB;
        #pragma unroll
        for (int i = 0; i < 4; ++i) {
            int r = ld_r + i * 32;
            uint32_t so = st_off + (uint32_t)(i * 32 * AST * 2);
            cp16(ab + so, g_Xhi + (size_t)(mtile * 128 + r) * 256 + kc + ld_c * 8);
            cp16(bb + so, g_Whi + (size_t)(ntile * 128 + r) * 256 + kc + ld_c * 8);
        }
    };

    load_stage(0, 0); cp_commit();
    load_stage(1, 1); cp_commit();

    for (int it = 0; it < 4; ++it) {
        int buf = it - (it / 3) * 3;        // it % 3
        if (it < 3) cp_wait<1>(); else cp_wait<0>();
        __syncthreads();
        if (it + 2 < 4) {
            int nb = (it + 2) - ((it + 2) / 3) * 3;
            load_stage(it + 2, nb);
            cp_commit();
        }

        uint32_t abuf = sb + (uint32_t)buf * STGB;
        uint32_t bbuf = abuf + TILEB;
        #pragma unroll
        for (int kk = 0; kk < 4; ++kk) {
            uint32_t afrag[4][4];
            #pragma unroll
            for (int mt = 0; mt < 4; ++mt) {
                uint32_t addr = abuf +
                    (uint32_t)(((a_row + mt * 16) * AST + kk * 16 + a_colp) * 2);
                ldsm_x4(afrag[mt][0], afrag[mt][1], afrag[mt][2], afrag[mt][3], addr);
            }
            uint32_t bfrag[2][4];
            #pragma unroll
            for (int nb = 0; nb < 2; ++nb) {
                uint32_t addr = bbuf +
                    (uint32_t)(((warp_n * 32 + nb * 16 + b_rowl) * AST + kk * 16 + b_colp) * 2);
                ldsm_x4(bfrag[nb][0], bfrag[nb][1], bfrag[nb][2], bfrag[nb][3], addr);
            }
            #pragma unroll
            for (int mt = 0; mt < 4; ++mt)
                #pragma unroll
                for (int nt = 0; nt < 4; ++nt)
                    mma16816(acc[mt][nt], afrag[mt],
                             bfrag[nt >> 1][(nt & 1) * 2],
                             bfrag[nt >> 1][(nt & 1) * 2 + 1]);
        }
    }

    // epilogue: pair (even,odd) N' columns -> |y|^2 / ||x||^2
    int r0 = mtile * 128 + warp_m * 64 + (lane >> 2);
    int cb = ntile * 64 + warp_n * 16 + (lane & 3);
    #pragma unroll
    for (int mt = 0; mt < 4; ++mt) {
        int row = r0 + mt * 16;
        float inv0 = 1.0f / g_norm2[row];
        float inv8 = 1.0f / g_norm2[row + 8];
        #pragma unroll
        for (int nt = 0; nt < 4; ++nt) {
            int colc = cb + nt * 4;
            float* dd = acc[mt][nt];
            out[(size_t)row * NDIM + colc]       = (dd[0] * dd[0] + dd[1] * dd[1]) * inv0;
            out[(size_t)(row + 8) * NDIM + colc] = (dd[2] * dd[2] + dd[3] * dd[3]) * inv8;
        }
    }
}

// ---------------- launcher ---------------------------------------------------
extern "C" void kernel_launch(void* const* d_in, const int* in_sizes, int n_in,
                              void* d_out, int out_size) {
    const float* x      = (const float*)d_in[0];
    const float* rots1  = (const float*)d_in[1];
    const float* phases = (const float*)d_in[2];
    const float* rots2  = (const float*)d_in[3];
    float* out = (float*)d_out;

    cudaFuncSetAttribute(k_gemm_tc, cudaFuncAttributeMaxDynamicSharedMemorySize,
                         GEMM_SMEM);

    k_misc<<<8192 + 128, 256>>>((const float4*)x, rots1, rots2);   // 1
    k_build_chunk<<<64, 32>>>();                                   // 2
    k_combine<<<dim3(4, 4, 4), 256>>>(0, phases);                  // 3
    k_combine<<<dim3(4, 4, 2), 256>>>(1, phases);                  // 4
    k_combine<<<dim3(4, 4, 2), 256>>>(2, phases);                  // 5
    k_gemm_tc<<<dim3(BATCH / 128, 4), 256, GEMM_SMEM>>>(out);      // 6 -> profiled
}

// round 17
// speedup vs baseline: 1.1788x; 1.1788x over previous
#include <cuda_runtime.h>
#include <cuda_fp16.h>
#include <stdint.h>
#include <math.h>

#define NDIM  256
#define NROT  32640
#define BATCH 65536

// ---------------- scratch (device globals; no allocation allowed) ----------
__device__ float2 g_cs1[NROT];
__device__ float2 g_cs2[NROT];
__device__ float  g_chunks[2 * 8 * NDIM * NDIM];
__device__ float  g_q[2 * 4 * NDIM * NDIM];
__device__ float  g_r[2 * 2 * NDIM * NDIM];
__device__ float  g_M1[NDIM * NDIM];
__device__ float  g_M2[NDIM * NDIM];
__device__ float  g_norm2[BATCH];

__device__ __half g_Xhi[BATCH * NDIM];             // fp16 X
__device__ __half g_Whi[2 * NDIM * NDIM];          // N'=512 (even=Re, odd=Im)

__constant__ int c_bound[9] = {0, 16, 34, 53, 74, 99, 127, 165, 255};

// ---------------- PTX helpers ------------------------------------------------
__device__ __forceinline__ uint32_t smem_u32(const void* p) {
    uint32_t a;
    asm("{ .reg .u64 t; cvta.to.shared.u64 t, %1; cvt.u32.u64 %0, t; }"
        : "=r"(a) : "l"(p));
    return a;
}

__device__ __forceinline__ void cp16(uint32_t dst, const void* src) {
    asm volatile("cp.async.cg.shared.global [%0], [%1], 16;" :: "r"(dst), "l"(src));
}
__device__ __forceinline__ void cp_commit() {
    asm volatile("cp.async.commit_group;");
}
template <int N>
__device__ __forceinline__ void cp_wait() {
    asm volatile("cp.async.wait_group %0;" :: "n"(N));
}

__device__ __forceinline__ void mma16816(float* d, const uint32_t* a,
                                         uint32_t b0, uint32_t b1) {
    asm volatile(
        "mma.sync.aligned.m16n8k16.row.col.f32.f16.f16.f32 "
        "{%0,%1,%2,%3}, {%4,%5,%6,%7}, {%8,%9}, {%0,%1,%2,%3};"
        : "+f"(d[0]), "+f"(d[1]), "+f"(d[2]), "+f"(d[3])
        : "r"(a[0]), "r"(a[1]), "r"(a[2]), "r"(a[3]), "r"(b0), "r"(b1));
}

__device__ __forceinline__ void ldsm_x4(uint32_t& r0, uint32_t& r1,
                                        uint32_t& r2, uint32_t& r3,
                                        uint32_t addr) {
    asm volatile("ldmatrix.sync.aligned.m8n8.x4.shared.b16 {%0,%1,%2,%3}, [%4];"
                 : "=r"(r0), "=r"(r1), "=r"(r2), "=r"(r3) : "r"(addr));
}

// ---------------- 1) cos/sin --------------------------------------------------
__global__ void k_sincos(const float* __restrict__ rots1,
                         const float* __restrict__ rots2) {
    int i = blockIdx.x * blockDim.x + threadIdx.x;
    if (i < NROT) {
        float s, c;
        sincosf(rots1[i], &s, &c);
        g_cs1[i] = make_float2(c, s);
        sincosf(rots2[i], &s, &c);
        g_cs2[i] = make_float2(c, s);
    }
}

// ---------------- 2a) build 8 chunk products per matrix ----------------------
__global__ void k_build_chunk() {
    __shared__ float col[NDIM * 32];
    int t = threadIdx.x;
    int b = blockIdx.x;
    int mat = b >> 6;
    int rem = b & 63;
    int chunk = rem >> 3;
    int cg = rem & 7;
    int c = cg * 32 + t;

    int a = c_bound[chunk];
    int e = c_bound[chunk + 1];

    const float2* __restrict__ cs = mat ? g_cs2 : g_cs1;
    float* __restrict__ P = g_chunks + (size_t)(mat * 8 + chunk) * (NDIM * NDIM);

    for (int r = 0; r < NDIM; ++r)
        col[r * 32 + t] = (r == c) ? 1.0f : 0.0f;

    int ridx = a * 255 - (a * (a - 1)) / 2;
    for (int i = a; i < e; ++i) {
        float acc = col[i * 32 + t];
        #pragma unroll 8
        for (int j = i + 1; j < NDIM; ++j) {
            float2 v = __ldg(&cs[ridx]);
            ++ridx;
            float vj = col[j * 32 + t];
            col[j * 32 + t] = v.y * acc + v.x * vj;
            acc = v.x * acc - v.y * vj;
        }
        col[i * 32 + t] = acc;
    }

    for (int r = 0; r < NDIM; ++r)
        P[r * NDIM + c] = col[r * 32 + t];
}

// ---------------- 2b) combine chunks: register-prefetch pipeline -------------
__global__ __launch_bounds__(256) void k_combine(int step) {
    __shared__ float Asm[64][33];
    __shared__ float Bsm[32][65];

    int z = blockIdx.z;
    const float *A, *B;
    float* C;
    if (step == 0) {
        int mat = z >> 2, p = z & 3;
        A = g_chunks + (size_t)(mat * 8 + 2 * p + 1) * (NDIM * NDIM);
        B = g_chunks + (size_t)(mat * 8 + 2 * p) * (NDIM * NDIM);
        C = g_q + (size_t)(mat * 4 + p) * (NDIM * NDIM);
    } else if (step == 1) {
        int mat = z >> 1, p = z & 1;
        A = g_q + (size_t)(mat * 4 + 2 * p + 1) * (NDIM * NDIM);
        B = g_q + (size_t)(mat * 4 + 2 * p) * (NDIM * NDIM);
        C = g_r + (size_t)(mat * 2 + p) * (NDIM * NDIM);
    } else {
        int mat = z;
        A = g_r + (size_t)(mat * 2 + 1) * (NDIM * NDIM);
        B = g_r + (size_t)(mat * 2 + 0) * (NDIM * NDIM);
        C = mat ? g_M2 : g_M1;
    }

    int tid = threadIdx.x;
    int tx = tid & 15, ty = tid >> 4;
    int row0 = blockIdx.y * 64;
    int col0 = blockIdx.x * 64;

    int ar = tid >> 2, aq = tid & 3;
    int br = tid >> 3, bq = tid & 7;

    float acc[4][4];
    #pragma unroll
    for (int i = 0; i < 4; ++i)
        #pragma unroll
        for (int j = 0; j < 4; ++j) acc[i][j] = 0.f;

    float4 pa0, pa1, pb0, pb1;
    {
        const float4* ap = (const float4*)&A[(row0 + ar) * NDIM];
        pa0 = ap[aq * 2]; pa1 = ap[aq * 2 + 1];
        const float4* bp = (const float4*)&B[(size_t)br * NDIM + col0];
        pb0 = bp[bq * 2]; pb1 = bp[bq * 2 + 1];
    }

    for (int kc = 0; kc < 8; ++kc) {
        __syncthreads();
        Asm[ar][aq * 8 + 0] = pa0.x; Asm[ar][aq * 8 + 1] = pa0.y;
        Asm[ar][aq * 8 + 2] = pa0.z; Asm[ar][aq * 8 + 3] = pa0.w;
        Asm[ar][aq * 8 + 4] = pa1.x; Asm[ar][aq * 8 + 5] = pa1.y;
        Asm[ar][aq * 8 + 6] = pa1.z; Asm[ar][aq * 8 + 7] = pa1.w;
        Bsm[br][bq * 8 + 0] = pb0.x; Bsm[br][bq * 8 + 1] = pb0.y;
        Bsm[br][bq * 8 + 2] = pb0.z; Bsm[br][bq * 8 + 3] = pb0.w;
        Bsm[br][bq * 8 + 4] = pb1.x; Bsm[br][bq * 8 + 5] = pb1.y;
        Bsm[br][bq * 8 + 6] = pb1.z; Bsm[br][bq * 8 + 7] = pb1.w;
        __syncthreads();

        if (kc < 7) {
            const float4* ap = (const float4*)&A[(row0 + ar) * NDIM + (kc + 1) * 32];
            pa0 = ap[aq * 2]; pa1 = ap[aq * 2 + 1];
            const float4* bp = (const float4*)&B[(size_t)((kc + 1) * 32 + br) * NDIM + col0];
            pb0 = bp[bq * 2]; pb1 = bp[bq * 2 + 1];
        }

        #pragma unroll 8
        for (int m = 0; m < 32; ++m) {
            float arr[4], brr[4];
            #pragma unroll
            for (int i = 0; i < 4; ++i) arr[i] = Asm[ty * 4 + i][m];
            #pragma unroll
            for (int j = 0; j < 4; ++j) brr[j] = Bsm[m][tx * 4 + j];
            #pragma unroll
            for (int i = 0; i < 4; ++i)
                #pragma unroll
                for (int j = 0; j < 4; ++j) acc[i][j] += arr[i] * brr[j];
        }
    }

    #pragma unroll
    for (int i = 0; i < 4; ++i)
        #pragma unroll
        for (int j = 0; j < 4; ++j)
            C[(size_t)(row0 + ty * 4 + i) * NDIM + col0 + tx * 4 + j] = acc[i][j];
}

// ---------------- 3) compose W = M2 diag(e^{i phi}) M1 -> fp16 interleaved ---
__global__ void k_compose(const float* __restrict__ phases) {
    __shared__ float sa[8][NDIM];
    __shared__ float sb[8][NDIM];
    int t = threadIdx.x;
    int n0 = blockIdx.x * 8;

    float sp, cp;
    sincosf(phases[t], &sp, &cp);
    #pragma unroll
    for (int r = 0; r < 8; ++r) {
        float m2 = g_M2[(n0 + r) * NDIM + t];
        sa[r][t] = m2 * cp;
        sb[r][t] = m2 * sp;
    }
    __syncthreads();

    float are[8], aim[8];
    #pragma unroll
    for (int r = 0; r < 8; ++r) { are[r] = 0.f; aim[r] = 0.f; }

    for (int m = 0; m < NDIM; ++m) {
        float m1 = g_M1[m * NDIM + t];
        #pragma unroll
        for (int r = 0; r < 8; ++r) {
            are[r] += sa[r][m] * m1;
            aim[r] += sb[r][m] * m1;
        }
    }
    #pragma unroll
    for (int r = 0; r < 8; ++r) {
        int n = n0 + r;
        g_Whi[(size_t)(2 * n) * NDIM + t]     = __float2half(are[r]);
        g_Whi[(size_t)(2 * n + 1) * NDIM + t] = __float2half(aim[r]);
    }
}

// ---------------- 4) fused X fp16 conversion + row norms ---------------------
__global__ void k_convx_norm(const float4* __restrict__ x4) {
    int w = threadIdx.x >> 5;
    int lane = threadIdx.x & 31;
    int row = blockIdx.x * 8 + w;
    const float4* p = x4 + (size_t)row * 64;
    float4 va = p[lane];
    float4 vb = p[lane + 32];

    float s = va.x * va.x + va.y * va.y + va.z * va.z + va.w * va.w
            + vb.x * vb.x + vb.y * vb.y + vb.z * vb.z + vb.w * vb.w;
    #pragma unroll
    for (int o = 16; o; o >>= 1) s += __shfl_xor_sync(0xffffffffu, s, o);
    if (lane == 0) g_norm2[row] = s;

    __half2* Ph = (__half2*)(g_Xhi + (size_t)row * NDIM);
    #pragma unroll
    for (int half = 0; half < 2; ++half) {
        float4 v = half ? vb : va;
        int base = (lane + half * 32) * 2;
        Ph[base + 0] = __halves2half2(__float2half(v.x), __float2half(v.y));
        Ph[base + 1] = __halves2half2(__float2half(v.z), __float2half(v.w));
    }
}

// ---------------- 5) X-resident GEMM: A tile smem-persistent, B streamed -----
// grid (512): CTA owns mtile, loops all 4 ntiles (N'=512 total).
// smem: A = 4 k-chunks (73728 B, loaded once) + B double buffer (2 x 18432 B).
// 16 B-stages: g = nt*4 + s; B[g] -> buf g&1; prefetch B[g+2] after compute g.
#define AST   72                         // fp16 row stride
#define TILEB (128 * AST * 2)            // 18432 B per tile
#define A_FULL (4 * TILEB)               // 73728 B
#define GEMM_SMEM (A_FULL + 2 * TILEB)   // 110592 B

__global__ __launch_bounds__(256, 2) void k_gemm_tc(float* __restrict__ out) {
    extern __shared__ __align__(16) char smem[];
    uint32_t sb = smem_u32(smem);

    int tid = threadIdx.x;
    int wid = tid >> 5, lane = tid & 31;
    int warp_m = wid >> 2;          // 0..1
    int warp_n = wid & 3;           // 0..3
    int mtile = blockIdx.x;         // 0..511

    float acc[4][4][4];
    #pragma unroll
    for (int mt = 0; mt < 4; ++mt)
        #pragma unroll
        for (int nt = 0; nt < 4; ++nt)
            #pragma unroll
            for (int q = 0; q < 4; ++q) acc[mt][nt][q] = 0.f;

    int a_row  = warp_m * 64 + (lane & 15);
    int a_colp = (lane >> 4) * 8;
    int b_rowl = ((lane >> 4) << 3) + (lane & 7);
    int b_colp = ((lane >> 3) & 1) * 8;

    int ld_r = tid >> 3;            // row 0..31 (+32*i)
    int ld_c = tid & 7;             // chunk 0..7
    uint32_t st_off = (uint32_t)(ld_r * (AST * 2) + ld_c * 16);

    // ---- load entire A tile (128 x 256 fp16) once: 4 k-chunks ----
    #pragma unroll
    for (int c = 0; c < 4; ++c)
        #pragma unroll
        for (int i = 0; i < 4; ++i) {
            int r = ld_r + i * 32;
            cp16(sb + (uint32_t)c * TILEB + st_off + (uint32_t)(i * 32 * AST * 2),
                 g_Xhi + (size_t)(mtile * 128 + r) * 256 + c * 64 + ld_c * 8);
        }
    cp_commit();

    auto load_B = [&](int g) {
        int nt = g >> 2, kc = (g & 3) * 64, buf = g & 1;
        uint32_t bb = sb + A_FULL + (uint32_t)buf * TILEB;
        #pragma unroll
        for (int i = 0; i < 4; ++i) {
            int r = ld_r + i * 32;
            cp16(bb + st_off + (uint32_t)(i * 32 * AST * 2),
                 g_Whi + (size_t)(nt * 128 + r) * 256 + kc + ld_c * 8);
        }
        cp_commit();
    };

    load_B(0);
    load_B(1);

    for (int g = 0; g < 16; ++g) {
        if (g < 15) cp_wait<1>(); else cp_wait<0>();
        __syncthreads();

        uint32_t abuf = sb + (uint32_t)(g & 3) * TILEB;
        uint32_t bbuf = sb + A_FULL + (uint32_t)(g & 1) * TILEB;
        #pragma unroll
        for (int kk = 0; kk < 4; ++kk) {
            uint32_t afrag[4][4];
            #pragma unroll
            for (int mt = 0; mt < 4; ++mt) {
                uint32_t addr = abuf +
                    (uint32_t)(((a_row + mt * 16) * AST + kk * 16 + a_colp) * 2);
                ldsm_x4(afrag[mt][0], afrag[mt][1], afrag[mt][2], afrag[mt][3], addr);
            }
            uint32_t bfrag[2][4];
            #pragma unroll
            for (int nb = 0; nb < 2; ++nb) {
                uint32_t addr = bbuf +
                    (uint32_t)(((warp_n * 32 + nb * 16 + b_rowl) * AST + kk * 16 + b_colp) * 2);
                ldsm_x4(bfrag[nb][0], bfrag[nb][1], bfrag[nb][2], bfrag[nb][3], addr);
            }
            #pragma unroll
            for (int mt = 0; mt < 4; ++mt)
                #pragma unroll
                for (int nt = 0; nt < 4; ++nt)
                    mma16816(acc[mt][nt], afrag[mt],
                             bfrag[nt >> 1][(nt & 1) * 2],
                             bfrag[nt >> 1][(nt & 1) * 2 + 1]);
        }
        __syncthreads();                 // protect buf (g&1) before reload
        if (g + 2 < 16) load_B(g + 2);   // overlaps next stage's compute

        if ((g & 3) == 3) {
            // ---- epilogue for completed ntile ----
            int ntile = g >> 2;
            int r0 = mtile * 128 + warp_m * 64 + (lane >> 2);
            int cb = ntile * 64 + warp_n * 16 + (lane & 3);
            #pragma unroll
            for (int mt = 0; mt < 4; ++mt) {
                int row = r0 + mt * 16;
                float inv0 = 1.0f / g_norm2[row];
                float inv8 = 1.0f / g_norm2[row + 8];
                #pragma unroll
                for (int nt = 0; nt < 4; ++nt) {
                    int colc = cb + nt * 4;
                    float* dd = acc[mt][nt];
                    out[(size_t)row * NDIM + colc] =
                        (dd[0] * dd[0] + dd[1] * dd[1]) * inv0;
                    out[(size_t)(row + 8) * NDIM + colc] =
                        (dd[2] * dd[2] + dd[3] * dd[3]) * inv8;
                    dd[0] = 0.f; dd[1] = 0.f; dd[2] = 0.f; dd[3] = 0.f;
                }
            }
        }
    }
}

// ---------------- launcher ---------------------------------------------------
extern "C" void kernel_launch(void* const* d_in, const int* in_sizes, int n_in,
                              void* d_out, int out_size) {
    const float* x      = (const float*)d_in[0];
    const float* rots1  = (const float*)d_in[1];
    const float* phases = (const float*)d_in[2];
    const float* rots2  = (const float*)d_in[3];
    float* out = (float*)d_out;

    cudaFuncSetAttribute(k_gemm_tc, cudaFuncAttributeMaxDynamicSharedMemorySize,
                         GEMM_SMEM);

    k_sincos<<<(NROT + 255) / 256, 256>>>(rots1, rots2);
    k_build_chunk<<<128, 32>>>();
    k_combine<<<dim3(4, 4, 8), 256>>>(0);
    k_combine<<<dim3(4, 4, 4), 256>>>(1);
    k_combine<<<dim3(4, 4, 2), 256>>>(2);
    k_compose<<<NDIM / 8, NDIM>>>(phases);
    k_convx_norm<<<BATCH / 8, 256>>>((const float4*)x);
    k_gemm_tc<<<512, 256, GEMM_SMEM>>>(out);
}